// round 11
// baseline (speedup 1.0000x reference)
#include <cuda_runtime.h>
#include <cuda_bf16.h>
#include <math.h>
#include <stdint.h>

// ---------------------------------------------------------------------------
// GConvLSTM (ChebConv K=3, lambda_max=2) on GB300.
//
// Identity: Lhat(v) = -A v  (lambda_max == 2), so
//   cheb(v,W,b) = v@(W0-W2) + (Av)@(-W1) + (A^2 v)@(2*W2) + b
// Pipeline (9 launches):
//   1. init  (U init + zero counters + dtype detect + weight combine)
//   2. deg   3. scan1(+dinv)  4. scan2  5. scan3   6. scatter CSR
//   7/8. pull-SpMM x2
//   9. mma.sync bf16x3 GEMM (64-row CTAs, 2 CTAs/SM) + fused LSTM epilogue
// (tcgen05 rejected by the harness's compute_103 PTX target -> legacy HMMA.)
// ---------------------------------------------------------------------------

#define N_  50000
#define E_  800000
#define NBLK ((N_ + 1023) / 1024)   // 49 scan blocks

typedef unsigned long long ull;

__device__ float g_U[(size_t)N_ * 384];   // [X|AX|A2X|H|AH|A2H] per row
__device__ float g_deg[N_];
__device__ float g_dinv[N_];
__device__ int   g_cnt[N_];
__device__ int   g_fill[N_];
__device__ int   g_rofs[N_ + 1];
__device__ int   g_bsum[64];
__device__ int2  g_cw[E_];                // packed {col, bits(w)}
__device__ __align__(16) __nv_bfloat16 g_Bh[256 * 384]; // B[n][k] hi
__device__ __align__(16) __nv_bfloat16 g_Bl[256 * 384]; // B[n][k] lo
__device__ float g_bias[256];             // [j][g]
__device__ int   g_is64;

// ---------------- helpers ----------------
__device__ __forceinline__ float sigm_(float z) {
    return 1.0f / (1.0f + __expf(-z));
}
__device__ __forceinline__ float tanh_(float z) {       // NaN-free at +/-inf
    return 1.0f - 2.0f / (1.0f + __expf(2.0f * z));
}
__device__ __forceinline__ int load_idx(const void* ei, long long pos, int is64) {
    if (is64) return (int)((const long long*)ei)[pos];
    return ((const int*)ei)[pos];
}
__device__ __forceinline__ uint32_t bfpack(float a, float b) {
    __nv_bfloat16 x = __float2bfloat16(a), y = __float2bfloat16(b);
    return (uint32_t)__bfloat16_as_ushort(x) |
           ((uint32_t)__bfloat16_as_ushort(y) << 16);
}
__device__ __forceinline__ float bflo(float v) {   // v - bf16(v)
    return v - __bfloat162float(__float2bfloat16(v));
}

#define MMA_BF16(d, a0, a1, a2, a3, b0, b1)                                   \
    asm volatile("mma.sync.aligned.m16n8k16.row.col.f32.bf16.bf16.f32 "       \
        "{%0,%1,%2,%3}, {%4,%5,%6,%7}, {%8,%9}, {%0,%1,%2,%3};"               \
        : "+f"((d)[0]), "+f"((d)[1]), "+f"((d)[2]), "+f"((d)[3])              \
        : "r"(a0), "r"(a1), "r"(a2), "r"(a3), "r"(b0), "r"(b1))

// ---------------- 1. init: U + counters + detect + combine ----------------
struct GPtrs {
    const float* Wx[4];  // Wxi, Wxf, Wxc, Wxo  each [3][64][64]
    const float* Wh[4];
    const float* bx[4];
    const float* bh[4];
    const float* bg[4];  // bi, bf, bc, bo each [64]
};

__global__ void k_init_u(const float* __restrict__ X, const float* __restrict__ H,
                         const int* __restrict__ ei, GPtrs p) {
    int idx = blockIdx.x * 256 + threadIdx.x;       // float4 units, N*32 total
    // dtype detect (one thread)
    if (idx == 0) {
        int s = 0;
        for (int i = 0; i < 64; i++) s |= ei[2 * i + 1];
        g_is64 = (s == 0) ? 1 : 0;
    }
    // zero counters
    if (idx < N_) { g_deg[idx] = 0.0f; g_cnt[idx] = 0; g_fill[idx] = 0; }
    // weight combine -> bf16 hi/lo B[n][k], n = j*4+g
    if (idx < 384 * 256) {
        int k = idx >> 8;
        int rem = idx & 255;
        int j = rem >> 2, g = rem & 3;
        int s = k / 64, kk = k % 64;
        const float* W = (s < 3) ? p.Wx[g] : p.Wh[g];
        int ss = s % 3;
        float val;
        if (ss == 0)      val = W[kk * 64 + j] - W[2 * 4096 + kk * 64 + j];
        else if (ss == 1) val = -W[4096 + kk * 64 + j];
        else              val = 2.0f * W[2 * 4096 + kk * 64 + j];
        int n = j * 4 + g;
        __nv_bfloat16 h = __float2bfloat16(val);
        g_Bh[(size_t)n * 384 + k] = h;
        g_Bl[(size_t)n * 384 + k] = __float2bfloat16(val - __bfloat162float(h));
    } else if (idx < 384 * 256 + 256) {
        int r = idx - 384 * 256;
        int j = r >> 2, g = r & 3;
        g_bias[j * 4 + g] = p.bx[g][j] + p.bh[g][j] + p.bg[g][j];
    }
    // U init
    if (idx >= N_ * 32) return;
    int row = idx >> 5, c4 = idx & 31;
    float4 v;
    int dst;
    if (c4 < 16) { v = ((const float4*)X)[row * 16 + c4];        dst = row * 96 + c4; }
    else         { v = ((const float4*)H)[row * 16 + (c4 - 16)]; dst = row * 96 + 32 + c4; }
    ((float4*)g_U)[dst] = v;
}

// ---------------- 2. degree + count ----------------
__global__ void k_deg(const void* __restrict__ ei, const float* __restrict__ ew) {
    int e = blockIdx.x * 256 + threadIdx.x;
    if (e >= E_) return;
    int is64 = g_is64;
    int r = load_idx(ei, e, is64);
    atomicAdd(&g_deg[r], ew[e]);
    atomicAdd(&g_cnt[r], 1);
}

// ---------------- 3-5. parallel scan (+dinv in scan1) ----------------
__global__ __launch_bounds__(1024) void k_scan1() {   // 49 blocks
    __shared__ int sh[1024];
    int b = blockIdx.x, t = threadIdx.x;
    int i = b * 1024 + t;
    if (i < N_) {
        float d = g_deg[i];
        g_dinv[i] = (d > 0.0f) ? rsqrtf(d) : 0.0f;
    }
    sh[t] = (i < N_) ? g_cnt[i] : 0;
    __syncthreads();
    for (int off = 512; off > 0; off >>= 1) {
        if (t < off) sh[t] += sh[t + off];
        __syncthreads();
    }
    if (t == 0) g_bsum[b] = sh[0];
}

__global__ void k_scan2() {                            // 1 block, 64 thr
    __shared__ int sh[64];
    int t = threadIdx.x;
    int v = (t < NBLK) ? g_bsum[t] : 0;
    sh[t] = v;
    __syncthreads();
    for (int off = 1; off < 64; off <<= 1) {
        int x = (t >= off) ? sh[t - off] : 0;
        __syncthreads();
        sh[t] += x;
        __syncthreads();
    }
    if (t < NBLK) g_bsum[t] = sh[t] - v;               // exclusive offsets
}

__global__ __launch_bounds__(1024) void k_scan3() {   // 49 blocks
    __shared__ int sh[1024];
    int b = blockIdx.x, t = threadIdx.x;
    int i = b * 1024 + t;
    int v = (i < N_) ? g_cnt[i] : 0;
    sh[t] = v;
    __syncthreads();
    for (int off = 1; off < 1024; off <<= 1) {         // inclusive scan
        int x = (t >= off) ? sh[t - off] : 0;
        __syncthreads();
        sh[t] += x;
        __syncthreads();
    }
    if (i < N_) g_rofs[i] = g_bsum[b] + sh[t] - v;     // exclusive
    if (b == 0 && t == 0) g_rofs[N_] = E_;
}

// ---------------- 6. scatter edges into CSR (packed int2) ----------------
__global__ void k_scatter(const void* __restrict__ ei, const float* __restrict__ ew) {
    int e = blockIdx.x * 256 + threadIdx.x;
    if (e >= E_) return;
    int is64 = g_is64;
    int r = load_idx(ei, e, is64);
    int c = load_idx(ei, (long long)E_ + e, is64);
    int pos = g_rofs[r] + atomicAdd(&g_fill[r], 1);
    float nw = g_dinv[r] * ew[e] * g_dinv[c];
    g_cw[pos] = make_int2(c, __float_as_int(nw));
}

// ---------------- 7/8. pull SpMM: one warp per row, 4-way edge unroll ----------
__global__ __launch_bounds__(256) void k_spmm_pull(int shift) {
    int row = (blockIdx.x * 256 + threadIdx.x) >> 5;
    if (row >= N_) return;
    int lane = threadIdx.x & 31;
    int off = (lane << 2) + ((lane >= 16) ? 128 : 0) + shift;

    int start = g_rofs[row];
    int end = g_rofs[row + 1];

    float4 a0 = make_float4(0.f, 0.f, 0.f, 0.f);
    float4 a1 = a0, a2 = a0, a3 = a0;

    int j = start;
    for (; j + 4 <= end; j += 4) {
        int2 cw0 = g_cw[j];
        int2 cw1 = g_cw[j + 1];
        int2 cw2 = g_cw[j + 2];
        int2 cw3 = g_cw[j + 3];
        const float4 v0 = *(const float4*)&g_U[(size_t)cw0.x * 384 + off];
        const float4 v1 = *(const float4*)&g_U[(size_t)cw1.x * 384 + off];
        const float4 v2 = *(const float4*)&g_U[(size_t)cw2.x * 384 + off];
        const float4 v3 = *(const float4*)&g_U[(size_t)cw3.x * 384 + off];
        float w0 = __int_as_float(cw0.y), w1 = __int_as_float(cw1.y);
        float w2 = __int_as_float(cw2.y), w3 = __int_as_float(cw3.y);
        a0.x += w0 * v0.x; a0.y += w0 * v0.y; a0.z += w0 * v0.z; a0.w += w0 * v0.w;
        a1.x += w1 * v1.x; a1.y += w1 * v1.y; a1.z += w1 * v1.z; a1.w += w1 * v1.w;
        a2.x += w2 * v2.x; a2.y += w2 * v2.y; a2.z += w2 * v2.z; a2.w += w2 * v2.w;
        a3.x += w3 * v3.x; a3.y += w3 * v3.y; a3.z += w3 * v3.z; a3.w += w3 * v3.w;
    }
    for (; j < end; ++j) {
        int2 cw = g_cw[j];
        float w = __int_as_float(cw.y);
        const float4 v = *(const float4*)&g_U[(size_t)cw.x * 384 + off];
        a0.x += w * v.x; a0.y += w * v.y; a0.z += w * v.z; a0.w += w * v.w;
    }
    a0.x += a1.x + a2.x + a3.x;
    a0.y += a1.y + a2.y + a3.y;
    a0.z += a1.z + a2.z + a3.z;
    a0.w += a1.w + a2.w + a3.w;
    *(float4*)&g_U[(size_t)row * 384 + off + 64] = a0;
}

// ---------------- 9. mma.sync bf16x3 GEMM + LSTM epilogue ----------------
// CTA: 64 rows x 256 cols, 256 threads (8 warps), 2 CTAs/SM for overlap.
// Warp (w&3) = m16 row block; (w>>2) = 128-col half; 16 n8 blocks/warp.
// K = 384 in 6 chunks of 64, 4 m16n8k16 k-steps/chunk, 3 MMAs/step
// (Ah*Bh + Al*Bh + Ah*Bl). Tiles [row][k] bf16, 144B pitch (conflict-free).
#define APITCH 144
#define A_HI_OFF 0
#define A_LO_OFF 9216
#define B_HI_OFF 18432
#define B_LO_OFF 55296
#define GEMM_SMEM 92160

__global__ __launch_bounds__(256, 2) void k_gemm_lstm_mma(const float* __restrict__ Cin,
                                                          float* __restrict__ out) {
    extern __shared__ char smx[];
    char* A_hi = smx + A_HI_OFF;
    char* A_lo = smx + A_LO_OFF;
    char* B_hi = smx + B_HI_OFF;
    char* B_lo = smx + B_LO_OFF;

    int t = threadIdx.x, lane = t & 31, wid = t >> 5;
    int m0 = blockIdx.x * 64;

    float acc[16][4];
#pragma unroll
    for (int nb = 0; nb < 16; nb++)
#pragma unroll
        for (int q = 0; q < 4; q++) acc[nb][q] = 0.0f;

    int mbase = (wid & 3) * 16;
    int nb128 = (wid >> 2) * 128;
    int r0 = lane >> 2, q2 = (lane & 3) * 2;

    for (int kc = 0; kc < 6; ++kc) {
        // ---- A: 64 rows x 64 k fp32 -> bf16 hi/lo (thread: r=t>>2, 16 k) ----
        {
            int r = t >> 2, kq = (t & 3) * 16;
            int row = m0 + r;
#pragma unroll
            for (int i = 0; i < 4; i++) {
                int k0 = kq + i * 4;
                float4 f = make_float4(0.f, 0.f, 0.f, 0.f);
                if (row < N_) f = *(const float4*)&g_U[(size_t)row * 384 + kc * 64 + k0];
                uint2 hv = make_uint2(bfpack(f.x, f.y), bfpack(f.z, f.w));
                uint2 lv = make_uint2(bfpack(bflo(f.x), bflo(f.y)),
                                      bfpack(bflo(f.z), bflo(f.w)));
                *(uint2*)(A_hi + r * APITCH + k0 * 2) = hv;
                *(uint2*)(A_lo + r * APITCH + k0 * 2) = lv;
            }
        }
        // ---- B: 256 n x 64 k bf16 hi/lo, straight copy (thread: n=t) ----
        {
            int n = t;
            const __nv_bfloat16* sh = &g_Bh[(size_t)n * 384 + kc * 64];
            const __nv_bfloat16* sl = &g_Bl[(size_t)n * 384 + kc * 64];
#pragma unroll
            for (int i = 0; i < 8; i++) {
                *(uint4*)(B_hi + n * APITCH + i * 16) = ((const uint4*)sh)[i];
                *(uint4*)(B_lo + n * APITCH + i * 16) = ((const uint4*)sl)[i];
            }
        }
        __syncthreads();

        int aoff = (mbase + r0) * APITCH + q2 * 2;
#pragma unroll
        for (int ks = 0; ks < 4; ks++) {
            int ab = aoff + ks * 32;
            uint32_t ah0 = *(const uint32_t*)(A_hi + ab);
            uint32_t ah1 = *(const uint32_t*)(A_hi + ab + 8 * APITCH);
            uint32_t ah2 = *(const uint32_t*)(A_hi + ab + 16);
            uint32_t ah3 = *(const uint32_t*)(A_hi + ab + 8 * APITCH + 16);
            uint32_t al0 = *(const uint32_t*)(A_lo + ab);
            uint32_t al1 = *(const uint32_t*)(A_lo + ab + 8 * APITCH);
            uint32_t al2 = *(const uint32_t*)(A_lo + ab + 16);
            uint32_t al3 = *(const uint32_t*)(A_lo + ab + 8 * APITCH + 16);
            int bbase = (nb128 + r0) * APITCH + q2 * 2 + ks * 32;
#pragma unroll
            for (int nb = 0; nb < 16; nb++) {
                int bo = bbase + nb * 8 * APITCH;
                uint32_t bh0 = *(const uint32_t*)(B_hi + bo);
                uint32_t bh1 = *(const uint32_t*)(B_hi + bo + 16);
                uint32_t bl0 = *(const uint32_t*)(B_lo + bo);
                uint32_t bl1 = *(const uint32_t*)(B_lo + bo + 16);
                MMA_BF16(acc[nb], ah0, ah1, ah2, ah3, bh0, bh1);
                MMA_BF16(acc[nb], al0, al1, al2, al3, bh0, bh1);
                MMA_BF16(acc[nb], ah0, ah1, ah2, ah3, bl0, bl1);
            }
        }
        __syncthreads();
    }

    // ---- epilogue: lane pair (xor 1) exchanges gates g2,g3; even lane
    //      computes LSTM for j = nb128/4 + nb*2 + ((lane>>1)&1) ----
    int jq = (lane >> 1) & 1;
#pragma unroll
    for (int nb = 0; nb < 16; nb++) {
        float p0 = __shfl_xor_sync(0xffffffffu, acc[nb][0], 1);
        float p1 = __shfl_xor_sync(0xffffffffu, acc[nb][1], 1);
        float p2 = __shfl_xor_sync(0xffffffffu, acc[nb][2], 1);
        float p3 = __shfl_xor_sync(0xffffffffu, acc[nb][3], 1);
        if ((lane & 1) == 0) {
            int j = (nb128 >> 2) + nb * 2 + jq;
            float4 bb = ((const float4*)g_bias)[j];
            int row = m0 + mbase + r0;
            if (row < N_) {
                float I = sigm_(acc[nb][0] + bb.x);
                float F = sigm_(acc[nb][1] + bb.y);
                float T = tanh_(p0 + bb.z);
                float O = sigm_(p1 + bb.w);
                float cn = F * Cin[(size_t)row * 64 + j] + I * T;
                out[(size_t)row * 64 + j] = O * tanh_(cn);
                out[(size_t)N_ * 64 + (size_t)row * 64 + j] = cn;
            }
            row += 8;
            if (row < N_) {
                float I = sigm_(acc[nb][2] + bb.x);
                float F = sigm_(acc[nb][3] + bb.y);
                float T = tanh_(p2 + bb.z);
                float O = sigm_(p3 + bb.w);
                float cn = F * Cin[(size_t)row * 64 + j] + I * T;
                out[(size_t)row * 64 + j] = O * tanh_(cn);
                out[(size_t)N_ * 64 + (size_t)row * 64 + j] = cn;
            }
        }
    }
}

// ---------------- launch ----------------
extern "C" void kernel_launch(void* const* d_in, const int* in_sizes, int n_in,
                              void* d_out, int out_size) {
    const float* X  = (const float*)d_in[0];
    const void*  EI = d_in[1];
    const float* EW = (const float*)d_in[2];
    const float* H  = (const float*)d_in[3];
    const float* C  = (const float*)d_in[4];

    GPtrs p;
    for (int g = 0; g < 4; g++) {
        p.Wx[g] = (const float*)d_in[5 + 4 * g];
        p.bx[g] = (const float*)d_in[6 + 4 * g];
        p.Wh[g] = (const float*)d_in[7 + 4 * g];
        p.bh[g] = (const float*)d_in[8 + 4 * g];
        p.bg[g] = (const float*)d_in[21 + g];
    }
    float* out = (float*)d_out;

    cudaFuncSetAttribute(k_gemm_lstm_mma,
                         cudaFuncAttributeMaxDynamicSharedMemorySize, GEMM_SMEM);

    k_init_u<<<(N_ * 32 + 255) / 256, 256>>>(X, H, (const int*)EI, p);
    k_deg<<<(E_ + 255) / 256, 256>>>(EI, EW);
    k_scan1<<<NBLK, 1024>>>();
    k_scan2<<<1, 64>>>();
    k_scan3<<<NBLK, 1024>>>();
    k_scatter<<<(E_ + 255) / 256, 256>>>(EI, EW);
    k_spmm_pull<<<(N_ * 32 + 255) / 256, 256>>>(0);
    k_spmm_pull<<<(N_ * 32 + 255) / 256, 256>>>(64);
    k_gemm_lstm_mma<<<(N_ + 63) / 64, 256, GEMM_SMEM>>>(C, out);
}

// round 12
// speedup vs baseline: 1.2379x; 1.2379x over previous
#include <cuda_runtime.h>
#include <cuda_bf16.h>
#include <math.h>
#include <stdint.h>

// ---------------------------------------------------------------------------
// GConvLSTM (ChebConv K=3, lambda_max=2) on GB300.
//
// Identity: Lhat(v) = -A v  (lambda_max == 2), so
//   cheb(v,W,b) = v@(W0-W2) + (Av)@(-W1) + (A^2 v)@(2*W2) + b
// Pipeline (7 launches):
//   1. init  (U init + zero counters + dtype detect + weight combine)
//   2. deg   3. scan (single kernel: dinv + block scan + aggregate publish)
//   4. scatter CSR   5/6. pull-SpMM x2
//   7. mma.sync bf16x3 GEMM (128-row CTAs, R8 shape) + fused LSTM epilogue
// (tcgen05 rejected by the harness's compute_103 PTX target -> legacy HMMA.)
// ---------------------------------------------------------------------------

#define N_  50000
#define E_  800000
#define NBLK ((N_ + 1023) / 1024)   // 49 scan blocks

typedef unsigned long long ull;

__device__ float g_U[(size_t)N_ * 384];   // [X|AX|A2X|H|AH|A2H] per row
__device__ float g_deg[N_];
__device__ float g_dinv[N_];
__device__ int   g_cnt[N_];
__device__ int   g_fill[N_];
__device__ int   g_rofs[N_ + 1];
__device__ volatile int g_agg[64];        // published block aggregates (+1)
__device__ int2  g_cw[E_];                // packed {col, bits(w)}
__device__ __align__(16) __nv_bfloat16 g_Bh[256 * 384]; // B[n][k] hi
__device__ __align__(16) __nv_bfloat16 g_Bl[256 * 384]; // B[n][k] lo
__device__ float g_bias[256];             // [j][g]
__device__ int   g_is64;

// ---------------- helpers ----------------
__device__ __forceinline__ float sigm_(float z) {
    return 1.0f / (1.0f + __expf(-z));
}
__device__ __forceinline__ float tanh_(float z) {       // NaN-free at +/-inf
    return 1.0f - 2.0f / (1.0f + __expf(2.0f * z));
}
__device__ __forceinline__ int load_idx(const void* ei, long long pos, int is64) {
    if (is64) return (int)((const long long*)ei)[pos];
    return ((const int*)ei)[pos];
}
__device__ __forceinline__ uint32_t bfpack(float a, float b) {
    __nv_bfloat16 x = __float2bfloat16(a), y = __float2bfloat16(b);
    return (uint32_t)__bfloat16_as_ushort(x) |
           ((uint32_t)__bfloat16_as_ushort(y) << 16);
}
__device__ __forceinline__ float bflo(float v) {   // v - bf16(v)
    return v - __bfloat162float(__float2bfloat16(v));
}

#define MMA_BF16(d, a0, a1, a2, a3, b0, b1)                                   \
    asm volatile("mma.sync.aligned.m16n8k16.row.col.f32.bf16.bf16.f32 "       \
        "{%0,%1,%2,%3}, {%4,%5,%6,%7}, {%8,%9}, {%0,%1,%2,%3};"               \
        : "+f"((d)[0]), "+f"((d)[1]), "+f"((d)[2]), "+f"((d)[3])              \
        : "r"(a0), "r"(a1), "r"(a2), "r"(a3), "r"(b0), "r"(b1))

// ---------------- 1. init: U + counters + detect + combine ----------------
struct GPtrs {
    const float* Wx[4];  // Wxi, Wxf, Wxc, Wxo  each [3][64][64]
    const float* Wh[4];
    const float* bx[4];
    const float* bh[4];
    const float* bg[4];  // bi, bf, bc, bo each [64]
};

__global__ void k_init_u(const float* __restrict__ X, const float* __restrict__ H,
                         const int* __restrict__ ei, GPtrs p) {
    int idx = blockIdx.x * 256 + threadIdx.x;       // float4 units, N*32 total
    // dtype detect (one thread)
    if (idx == 0) {
        int s = 0;
        for (int i = 0; i < 64; i++) s |= ei[2 * i + 1];
        g_is64 = (s == 0) ? 1 : 0;
    }
    // reset scan aggregates
    if (idx < 64) g_agg[idx] = 0;
    // zero counters
    if (idx < N_) { g_deg[idx] = 0.0f; g_cnt[idx] = 0; g_fill[idx] = 0; }
    // weight combine -> bf16 hi/lo B[n][k], n = j*4+g
    if (idx < 384 * 256) {
        int k = idx >> 8;
        int rem = idx & 255;
        int j = rem >> 2, g = rem & 3;
        int s = k / 64, kk = k % 64;
        const float* W = (s < 3) ? p.Wx[g] : p.Wh[g];
        int ss = s % 3;
        float val;
        if (ss == 0)      val = W[kk * 64 + j] - W[2 * 4096 + kk * 64 + j];
        else if (ss == 1) val = -W[4096 + kk * 64 + j];
        else              val = 2.0f * W[2 * 4096 + kk * 64 + j];
        int n = j * 4 + g;
        __nv_bfloat16 h = __float2bfloat16(val);
        g_Bh[(size_t)n * 384 + k] = h;
        g_Bl[(size_t)n * 384 + k] = __float2bfloat16(val - __bfloat162float(h));
    } else if (idx < 384 * 256 + 256) {
        int r = idx - 384 * 256;
        int j = r >> 2, g = r & 3;
        g_bias[j * 4 + g] = p.bx[g][j] + p.bh[g][j] + p.bg[g][j];
    }
    // U init
    if (idx >= N_ * 32) return;
    int row = idx >> 5, c4 = idx & 31;
    float4 v;
    int dst;
    if (c4 < 16) { v = ((const float4*)X)[row * 16 + c4];        dst = row * 96 + c4; }
    else         { v = ((const float4*)H)[row * 16 + (c4 - 16)]; dst = row * 96 + 32 + c4; }
    ((float4*)g_U)[dst] = v;
}

// ---------------- 2. degree + count ----------------
__global__ void k_deg(const void* __restrict__ ei, const float* __restrict__ ew) {
    int e = blockIdx.x * 256 + threadIdx.x;
    if (e >= E_) return;
    int is64 = g_is64;
    int r = load_idx(ei, e, is64);
    atomicAdd(&g_deg[r], ew[e]);
    atomicAdd(&g_cnt[r], 1);
}

// ---------------- 3. single-kernel scan: dinv + block scan + aggregates ----
// 49 blocks x 1024, all resident in one wave (49 <= 148 SMs). Each block
// publishes its aggregate unconditionally, then threads t<b poll agg[t]
// (published as agg+1 so nonzero) and sum into the block offset.
__global__ __launch_bounds__(1024) void k_scan() {
    __shared__ int sh[1024];
    __shared__ int s_off;
    int b = blockIdx.x, t = threadIdx.x;
    int i = b * 1024 + t;
    if (i < N_) {
        float d = g_deg[i];
        g_dinv[i] = (d > 0.0f) ? rsqrtf(d) : 0.0f;
    }
    int v = (i < N_) ? g_cnt[i] : 0;
    sh[t] = v;
    if (t == 0) s_off = 0;
    __syncthreads();
    for (int off = 1; off < 1024; off <<= 1) {          // inclusive scan
        int x = (t >= off) ? sh[t - off] : 0;
        __syncthreads();
        sh[t] += x;
        __syncthreads();
    }
    if (t == 1023) g_agg[b] = sh[1023] + 1;             // publish aggregate
    if (t < b) {                                        // poll predecessors
        int a;
        do { a = g_agg[t]; } while (a == 0);
        atomicAdd(&s_off, a - 1);
    }
    __syncthreads();
    if (i < N_) g_rofs[i] = s_off + sh[t] - v;          // exclusive
    if (b == 0 && t == 0) g_rofs[N_] = E_;
}

// ---------------- 4. scatter edges into CSR (packed int2) ----------------
__global__ void k_scatter(const void* __restrict__ ei, const float* __restrict__ ew) {
    int e = blockIdx.x * 256 + threadIdx.x;
    if (e >= E_) return;
    int is64 = g_is64;
    int r = load_idx(ei, e, is64);
    int c = load_idx(ei, (long long)E_ + e, is64);
    int pos = g_rofs[r] + atomicAdd(&g_fill[r], 1);
    float nw = g_dinv[r] * ew[e] * g_dinv[c];
    g_cw[pos] = make_int2(c, __float_as_int(nw));
}

// ---------------- 5/6. pull SpMM: one warp per row, 4-way edge unroll ----------
__global__ __launch_bounds__(256) void k_spmm_pull(int shift) {
    int row = (blockIdx.x * 256 + threadIdx.x) >> 5;
    if (row >= N_) return;
    int lane = threadIdx.x & 31;
    int off = (lane << 2) + ((lane >= 16) ? 128 : 0) + shift;

    int start = g_rofs[row];
    int end = g_rofs[row + 1];

    float4 a0 = make_float4(0.f, 0.f, 0.f, 0.f);
    float4 a1 = a0, a2 = a0, a3 = a0;

    int j = start;
    for (; j + 4 <= end; j += 4) {
        int2 cw0 = g_cw[j];
        int2 cw1 = g_cw[j + 1];
        int2 cw2 = g_cw[j + 2];
        int2 cw3 = g_cw[j + 3];
        const float4 v0 = *(const float4*)&g_U[(size_t)cw0.x * 384 + off];
        const float4 v1 = *(const float4*)&g_U[(size_t)cw1.x * 384 + off];
        const float4 v2 = *(const float4*)&g_U[(size_t)cw2.x * 384 + off];
        const float4 v3 = *(const float4*)&g_U[(size_t)cw3.x * 384 + off];
        float w0 = __int_as_float(cw0.y), w1 = __int_as_float(cw1.y);
        float w2 = __int_as_float(cw2.y), w3 = __int_as_float(cw3.y);
        a0.x += w0 * v0.x; a0.y += w0 * v0.y; a0.z += w0 * v0.z; a0.w += w0 * v0.w;
        a1.x += w1 * v1.x; a1.y += w1 * v1.y; a1.z += w1 * v1.z; a1.w += w1 * v1.w;
        a2.x += w2 * v2.x; a2.y += w2 * v2.y; a2.z += w2 * v2.z; a2.w += w2 * v2.w;
        a3.x += w3 * v3.x; a3.y += w3 * v3.y; a3.z += w3 * v3.z; a3.w += w3 * v3.w;
    }
    for (; j < end; ++j) {
        int2 cw = g_cw[j];
        float w = __int_as_float(cw.y);
        const float4 v = *(const float4*)&g_U[(size_t)cw.x * 384 + off];
        a0.x += w * v.x; a0.y += w * v.y; a0.z += w * v.z; a0.w += w * v.w;
    }
    a0.x += a1.x + a2.x + a3.x;
    a0.y += a1.y + a2.y + a3.y;
    a0.z += a1.z + a2.z + a3.z;
    a0.w += a1.w + a2.w + a3.w;
    *(float4*)&g_U[(size_t)row * 384 + off + 64] = a0;
}

// ---------------- 7. mma.sync bf16x3 GEMM + LSTM epilogue (R8 shape) -------
// CTA: 128 rows x 256 cols, 512 threads (16 warps), single-buffered.
// Warp (w&7) = m16 row block; (w>>3) = 128-col half; 16 n8 blocks/warp.
// K = 384 in 6 chunks of 64, 4 m16n8k16 k-steps/chunk, 3 MMAs/step
// (Ah*Bh + Al*Bh + Ah*Bl). Tiles [row][k] bf16, 144B pitch (conflict-free).
#define APITCH 144
#define A_HI_OFF 0
#define A_LO_OFF 18432
#define B_HI_OFF 36864
#define B_LO_OFF 73728
#define GEMM_SMEM 110592

__global__ __launch_bounds__(512, 1) void k_gemm_lstm_mma(const float* __restrict__ Cin,
                                                          float* __restrict__ out) {
    extern __shared__ char smx[];
    char* A_hi = smx + A_HI_OFF;
    char* A_lo = smx + A_LO_OFF;
    char* B_hi = smx + B_HI_OFF;
    char* B_lo = smx + B_LO_OFF;

    int t = threadIdx.x, lane = t & 31, wid = t >> 5;
    int m0 = blockIdx.x * 128;

    float acc[16][4];
#pragma unroll
    for (int nb = 0; nb < 16; nb++)
#pragma unroll
        for (int q = 0; q < 4; q++) acc[nb][q] = 0.0f;

    int mbase = (wid & 7) * 16;
    int nb128 = (wid >> 3) * 128;
    int r0 = lane >> 2, q2 = (lane & 3) * 2;

    for (int kc = 0; kc < 6; ++kc) {
        // ---- A: 128 rows x 64 k fp32 -> bf16 hi/lo (thread: r=t>>2, 16 k) ----
        {
            int r = t >> 2, kq = (t & 3) * 16;
            int row = m0 + r;
#pragma unroll
            for (int i = 0; i < 4; i++) {
                int k0 = kq + i * 4;
                float4 f = make_float4(0.f, 0.f, 0.f, 0.f);
                if (row < N_) f = *(const float4*)&g_U[(size_t)row * 384 + kc * 64 + k0];
                uint2 hv = make_uint2(bfpack(f.x, f.y), bfpack(f.z, f.w));
                uint2 lv = make_uint2(bfpack(bflo(f.x), bflo(f.y)),
                                      bfpack(bflo(f.z), bflo(f.w)));
                *(uint2*)(A_hi + r * APITCH + k0 * 2) = hv;
                *(uint2*)(A_lo + r * APITCH + k0 * 2) = lv;
            }
        }
        // ---- B: 256 n x 64 k bf16 hi/lo, straight copy (thread: n=t>>1) ----
        {
            int n = t >> 1, kh = (t & 1) * 32;
            const __nv_bfloat16* sh = &g_Bh[(size_t)n * 384 + kc * 64 + kh];
            const __nv_bfloat16* sl = &g_Bl[(size_t)n * 384 + kc * 64 + kh];
#pragma unroll
            for (int i = 0; i < 4; i++) {
                *(uint4*)(B_hi + n * APITCH + (kh + i * 8) * 2) = ((const uint4*)sh)[i];
                *(uint4*)(B_lo + n * APITCH + (kh + i * 8) * 2) = ((const uint4*)sl)[i];
            }
        }
        __syncthreads();

        int aoff = (mbase + r0) * APITCH + q2 * 2;
#pragma unroll
        for (int ks = 0; ks < 4; ks++) {
            int ab = aoff + ks * 32;
            uint32_t ah0 = *(const uint32_t*)(A_hi + ab);
            uint32_t ah1 = *(const uint32_t*)(A_hi + ab + 8 * APITCH);
            uint32_t ah2 = *(const uint32_t*)(A_hi + ab + 16);
            uint32_t ah3 = *(const uint32_t*)(A_hi + ab + 8 * APITCH + 16);
            uint32_t al0 = *(const uint32_t*)(A_lo + ab);
            uint32_t al1 = *(const uint32_t*)(A_lo + ab + 8 * APITCH);
            uint32_t al2 = *(const uint32_t*)(A_lo + ab + 16);
            uint32_t al3 = *(const uint32_t*)(A_lo + ab + 8 * APITCH + 16);
            int bbase = (nb128 + r0) * APITCH + q2 * 2 + ks * 32;
#pragma unroll
            for (int nb = 0; nb < 16; nb++) {
                int bo = bbase + nb * 8 * APITCH;
                uint32_t bh0 = *(const uint32_t*)(B_hi + bo);
                uint32_t bh1 = *(const uint32_t*)(B_hi + bo + 16);
                uint32_t bl0 = *(const uint32_t*)(B_lo + bo);
                uint32_t bl1 = *(const uint32_t*)(B_lo + bo + 16);
                MMA_BF16(acc[nb], ah0, ah1, ah2, ah3, bh0, bh1);
                MMA_BF16(acc[nb], al0, al1, al2, al3, bh0, bh1);
                MMA_BF16(acc[nb], ah0, ah1, ah2, ah3, bl0, bl1);
            }
        }
        __syncthreads();
    }

    // ---- epilogue: lane pair (xor 1) exchanges gates g2,g3; even lane
    //      computes LSTM for j = nb128/4 + nb*2 + ((lane>>1)&1) ----
    int jq = (lane >> 1) & 1;
#pragma unroll
    for (int nb = 0; nb < 16; nb++) {
        float p0 = __shfl_xor_sync(0xffffffffu, acc[nb][0], 1);
        float p1 = __shfl_xor_sync(0xffffffffu, acc[nb][1], 1);
        float p2 = __shfl_xor_sync(0xffffffffu, acc[nb][2], 1);
        float p3 = __shfl_xor_sync(0xffffffffu, acc[nb][3], 1);
        if ((lane & 1) == 0) {
            int j = (nb128 >> 2) + nb * 2 + jq;
            float4 bb = ((const float4*)g_bias)[j];
            int row = m0 + mbase + r0;
            if (row < N_) {
                float I = sigm_(acc[nb][0] + bb.x);
                float F = sigm_(acc[nb][1] + bb.y);
                float T = tanh_(p0 + bb.z);
                float O = sigm_(p1 + bb.w);
                float cn = F * Cin[(size_t)row * 64 + j] + I * T;
                out[(size_t)row * 64 + j] = O * tanh_(cn);
                out[(size_t)N_ * 64 + (size_t)row * 64 + j] = cn;
            }
            row += 8;
            if (row < N_) {
                float I = sigm_(acc[nb][2] + bb.x);
                float F = sigm_(acc[nb][3] + bb.y);
                float T = tanh_(p2 + bb.z);
                float O = sigm_(p3 + bb.w);
                float cn = F * Cin[(size_t)row * 64 + j] + I * T;
                out[(size_t)row * 64 + j] = O * tanh_(cn);
                out[(size_t)N_ * 64 + (size_t)row * 64 + j] = cn;
            }
        }
    }
}

// ---------------- launch ----------------
extern "C" void kernel_launch(void* const* d_in, const int* in_sizes, int n_in,
                              void* d_out, int out_size) {
    const float* X  = (const float*)d_in[0];
    const void*  EI = d_in[1];
    const float* EW = (const float*)d_in[2];
    const float* H  = (const float*)d_in[3];
    const float* C  = (const float*)d_in[4];

    GPtrs p;
    for (int g = 0; g < 4; g++) {
        p.Wx[g] = (const float*)d_in[5 + 4 * g];
        p.bx[g] = (const float*)d_in[6 + 4 * g];
        p.Wh[g] = (const float*)d_in[7 + 4 * g];
        p.bh[g] = (const float*)d_in[8 + 4 * g];
        p.bg[g] = (const float*)d_in[21 + g];
    }
    float* out = (float*)d_out;

    cudaFuncSetAttribute(k_gemm_lstm_mma,
                         cudaFuncAttributeMaxDynamicSharedMemorySize, GEMM_SMEM);

    k_init_u<<<(N_ * 32 + 255) / 256, 256>>>(X, H, (const int*)EI, p);
    k_deg<<<(E_ + 255) / 256, 256>>>(EI, EW);
    k_scan<<<NBLK, 1024>>>();
    k_scatter<<<(E_ + 255) / 256, 256>>>(EI, EW);
    k_spmm_pull<<<(N_ * 32 + 255) / 256, 256>>>(0);
    k_spmm_pull<<<(N_ * 32 + 255) / 256, 256>>>(64);
    k_gemm_lstm_mma<<<(N_ + 127) / 128, 512, GEMM_SMEM>>>(C, out);
}